// round 6
// baseline (speedup 1.0000x reference)
#include <cuda_runtime.h>
#include <math.h>
#include <stdint.h>

#define B_SZ  2
#define C_DIM 512
#define E_DIM 512
#define N_TOK 4096
#define NH    8
#define HD    64

// Scratch (all __device__ globals; no allocation).
__device__ float g_Q[B_SZ * E_DIM * N_TOK];
__device__ float g_K[B_SZ * E_DIM * N_TOK];
__device__ float g_V[B_SZ * E_DIM * N_TOK];
// tf32-rounded copies of proj inputs (cp.async feeds mma directly from these).
__device__ float g_TQ[B_SZ * C_DIM * N_TOK];
__device__ float g_TK[B_SZ * C_DIM * N_TOK];
__device__ float g_W[3 * E_DIM * C_DIM];

__device__ __forceinline__ float f2tff(float f) {
    uint32_t r;
    asm("cvt.rna.tf32.f32 %0, %1;" : "=r"(r) : "f"(f));
    return __uint_as_float(r);
}
__device__ __forceinline__ void mma_tf32(float* d, uint32_t a0, uint32_t a1,
                                         uint32_t a2, uint32_t a3,
                                         uint32_t b0, uint32_t b1) {
    asm volatile(
        "mma.sync.aligned.m16n8k8.row.col.f32.tf32.tf32.f32 "
        "{%0,%1,%2,%3}, {%4,%5,%6,%7}, {%8,%9}, {%0,%1,%2,%3};"
        : "+f"(d[0]), "+f"(d[1]), "+f"(d[2]), "+f"(d[3])
        : "r"(a0), "r"(a1), "r"(a2), "r"(a3), "r"(b0), "r"(b1));
}
__device__ __forceinline__ void cp16(float* dst, const float* src) {
    uint32_t d = (uint32_t)__cvta_generic_to_shared(dst);
    asm volatile("cp.async.cg.shared.global [%0], [%1], 16;"
                 :: "r"(d), "l"(src) : "memory");
}
__device__ __forceinline__ void cp_commit() {
    asm volatile("cp.async.commit_group;" ::: "memory");
}
__device__ __forceinline__ void cp_wait1() {
    asm volatile("cp.async.wait_group 1;" ::: "memory");
}

// ---------------------------------------------------------------------------
// tf32 rounding copy (vectorized, grid-stride). n must be /4.
// ---------------------------------------------------------------------------
__global__ void round_kernel(float* __restrict__ dst, const float* __restrict__ src,
                             int n4) {
    int i = blockIdx.x * blockDim.x + threadIdx.x;
    int stride = gridDim.x * blockDim.x;
    for (; i < n4; i += stride) {
        float4 v = ((const float4*)src)[i];
        v.x = f2tff(v.x); v.y = f2tff(v.y); v.z = f2tff(v.z); v.w = f2tff(v.w);
        ((float4*)dst)[i] = v;
    }
}

// ---------------------------------------------------------------------------
// Projection GEMM (tf32 mma, cp.async double-buffered; inputs pre-rounded).
// Block tile 128(e) x 128(n), K-chunk 32. Warp = 32e x 64n (2 m-tiles, 8 n-tiles).
// A=[e][c] ld 36, B=[c][n] ld 136.
// ---------------------------------------------------------------------------
__global__ __launch_bounds__(256, 2) void proj_kernel(
    const float* __restrict__ bq, const float* __restrict__ bk,
    const float* __restrict__ bv)
{
    extern __shared__ float sm[];
    float* As = sm;            // 2 x [128][36] = 9216 floats
    float* Bs = sm + 9216;     // 2 x [32][136] = 8704 floats

    const int tid = threadIdx.x;
    const int w = tid >> 5, lane = tid & 31;
    const int g = lane >> 2, t = lane & 3;
    const int wm = w & 3, wn = w >> 2;

    const int n0 = blockIdx.x * 128;
    const int e0 = blockIdx.y * 128;
    const int z  = blockIdx.z;
    const int b = z / 3, p = z % 3;

    const float* T    = (p == 0 ? g_TQ : g_TK) + (size_t)b * C_DIM * N_TOK;
    const float* W    = g_W + (size_t)p * E_DIM * C_DIM;
    const float* bias = (p == 0 ? bq : (p == 1 ? bk : bv));
    float* Out = (p == 0 ? g_Q : (p == 1 ? g_K : g_V)) + (size_t)b * E_DIM * N_TOK;

    const int NSTEP = C_DIM / 32;   // 16

    auto stage = [&](int s_iter) {
        if (s_iter < NSTEP) {
            int s = s_iter & 1;
            int c0 = s_iter * 32;
            #pragma unroll
            for (int r = 0; r < 4; r++) {        // A: 128 x 32
                int c = r * 256 + tid;
                int e = c >> 3, cc = c & 7;
                cp16(&As[s * 4608 + e * 36 + cc * 4],
                     W + (size_t)(e0 + e) * C_DIM + c0 + cc * 4);
            }
            #pragma unroll
            for (int r = 0; r < 4; r++) {        // B: 32 x 128
                int c = r * 256 + tid;
                int cr = c >> 5, nc = c & 31;
                cp16(&Bs[s * 4352 + cr * 136 + nc * 4],
                     T + (size_t)(c0 + cr) * N_TOK + n0 + nc * 4);
            }
        }
        cp_commit();
    };

    stage(0);

    float acc[2][8][4] = {};

    for (int ks = 0; ks < NSTEP; ks++) {
        __syncthreads();
        stage(ks + 1);
        cp_wait1();
        __syncthreads();

        const float* A = As + (ks & 1) * 4608;
        const float* Bt = Bs + (ks & 1) * 4352;

        #pragma unroll
        for (int kt = 0; kt < 4; kt++) {
            uint32_t a[2][4];
            #pragma unroll
            for (int mi = 0; mi < 2; mi++) {
                int ab = (wm * 32 + mi * 16 + g) * 36 + kt * 8 + t;
                a[mi][0] = __float_as_uint(A[ab]);
                a[mi][1] = __float_as_uint(A[ab + 8 * 36]);
                a[mi][2] = __float_as_uint(A[ab + 4]);
                a[mi][3] = __float_as_uint(A[ab + 8 * 36 + 4]);
            }
            #pragma unroll
            for (int nt = 0; nt < 8; nt++) {
                int bb = (kt * 8 + t) * 136 + wn * 64 + nt * 8 + g;
                uint32_t b0 = __float_as_uint(Bt[bb]);
                uint32_t b1 = __float_as_uint(Bt[bb + 4 * 136]);
                mma_tf32(acc[0][nt], a[0][0], a[0][1], a[0][2], a[0][3], b0, b1);
                mma_tf32(acc[1][nt], a[1][0], a[1][1], a[1][2], a[1][3], b0, b1);
            }
        }
    }

    #pragma unroll
    for (int mi = 0; mi < 2; mi++) {
        int e_lo = e0 + wm * 32 + mi * 16 + g;
        float b_lo = bias[e_lo], b_hi = bias[e_lo + 8];
        #pragma unroll
        for (int nt = 0; nt < 8; nt++) {
            int n = n0 + wn * 64 + nt * 8 + t * 2;
            *(float2*)(Out + (size_t)e_lo * N_TOK + n) =
                make_float2(f2tff(acc[mi][nt][0] + b_lo), f2tff(acc[mi][nt][1] + b_lo));
            *(float2*)(Out + (size_t)(e_lo + 8) * N_TOK + n) =
                make_float2(f2tff(acc[mi][nt][2] + b_hi), f2tff(acc[mi][nt][3] + b_hi));
        }
    }
}

// ---------------------------------------------------------------------------
// Flash attention, tf32 mma, cp.async double-buffered K/V.
// Block = (b, h, 256-query tile), 8 warps; warp owns 32 query rows (2 m-tiles).
// Bc=32. Layouts: Q [d=64][i=256] ld264, K [d][j=32] ld40, V [d][j] ld36,
// P [i=256][j] ld36. All fragment LDS conflict-free by stride choice.
// ---------------------------------------------------------------------------
__global__ __launch_bounds__(256, 1) void attn_kernel(float* __restrict__ out)
{
    extern __shared__ float sm[];
    float* Ks = sm;              // 2 x [64][40] = 5120
    float* Vs = sm + 5120;       // 2 x [64][36] = 4608
    float* Qs = sm + 9728;       // [64][264]    = 16896 (epilogue: O^T)
    float* Ps = sm + 26624;      // [256][36]    = 9216

    const int tid = threadIdx.x;
    const int w = tid >> 5, lane = tid & 31;
    const int g = lane >> 2, t = lane & 3;

    const int it = gridDim.x - 1 - blockIdx.x;   // heavy tiles first
    const int i0 = it * 256;
    const int h = blockIdx.y, b = blockIdx.z;

    const float* Qg = g_Q + ((size_t)b * E_DIM + h * HD) * N_TOK;
    const float* Kg = g_K + ((size_t)b * E_DIM + h * HD) * N_TOK;
    const float* Vg = g_V + ((size_t)b * E_DIM + h * HD) * N_TOK;

    const int njt = 8 * it + 8;

    auto stage = [&](int jt) {
        if (jt < njt) {
            int s = jt & 1;
            int j0 = jt * 32;
            #pragma unroll
            for (int r = 0; r < 2; r++) {        // K: 64 x 32
                int c = r * 256 + tid;
                int d = c >> 3, jc = c & 7;
                cp16(&Ks[s * 2560 + d * 40 + jc * 4],
                     Kg + (size_t)d * N_TOK + j0 + jc * 4);
            }
            #pragma unroll
            for (int r = 0; r < 2; r++) {        // V: 64 x 32
                int c = r * 256 + tid;
                int d = c >> 3, jc = c & 7;
                cp16(&Vs[s * 2304 + d * 36 + jc * 4],
                     Vg + (size_t)d * N_TOK + j0 + jc * 4);
            }
        }
        cp_commit();
    };

    stage(0);
    // Q staging: 64 x 256 via float4 (latency overlaps with cp.async above)
    #pragma unroll
    for (int r = 0; r < 16; r++) {
        int idx = r * 256 + tid;
        int d = idx >> 6, i4 = idx & 63;
        float4 v = *(const float4*)(Qg + (size_t)d * N_TOK + i0 + i4 * 4);
        *(float4*)&Qs[d * 264 + i4 * 4] = v;
    }

    float m[2][2], l[2][2];
    #pragma unroll
    for (int mi = 0; mi < 2; mi++) {
        m[mi][0] = -1e30f; m[mi][1] = -1e30f;
        l[mi][0] = 0.f;    l[mi][1] = 0.f;
    }
    float o[2][8][4] = {};
    const float scale = 0.125f;  // 1/sqrt(64)

    for (int jt = 0; jt < njt; jt++) {
        __syncthreads();          // prev reads of buffer (jt+1)&1 done; Q visible
        stage(jt + 1);
        cp_wait1();
        __syncthreads();

        const float* K = Ks + (jt & 1) * 2560;
        const float* V = Vs + (jt & 1) * 2304;
        const int j0 = jt * 32;

        // ---- S = Q K^T (32 x 32 per warp, 2 m-tiles) ----
        float s[2][4][4] = {};
        #pragma unroll
        for (int kt = 0; kt < 8; kt++) {
            uint32_t a[2][4];
            #pragma unroll
            for (int mi = 0; mi < 2; mi++) {
                int ab = (kt * 8 + t) * 264 + 32 * w + mi * 16 + g;
                a[mi][0] = __float_as_uint(Qs[ab]);
                a[mi][1] = __float_as_uint(Qs[ab + 8]);
                a[mi][2] = __float_as_uint(Qs[ab + 4 * 264]);
                a[mi][3] = __float_as_uint(Qs[ab + 4 * 264 + 8]);
            }
            #pragma unroll
            for (int nt = 0; nt < 4; nt++) {
                int bb = (kt * 8 + t) * 40 + nt * 8 + g;
                uint32_t b0 = __float_as_uint(K[bb]);
                uint32_t b1 = __float_as_uint(K[bb + 4 * 40]);
                mma_tf32(s[0][nt], a[0][0], a[0][1], a[0][2], a[0][3], b0, b1);
                mma_tf32(s[1][nt], a[1][0], a[1][1], a[1][2], a[1][3], b0, b1);
            }
        }

        // scale + causal mask (diagonal-region tiles only)
        #pragma unroll
        for (int mi = 0; mi < 2; mi++)
            #pragma unroll
            for (int nt = 0; nt < 4; nt++) {
                s[mi][nt][0] *= scale; s[mi][nt][1] *= scale;
                s[mi][nt][2] *= scale; s[mi][nt][3] *= scale;
            }
        if (jt >= 8 * it) {
            #pragma unroll
            for (int mi = 0; mi < 2; mi++) {
                int r_lo = i0 + 32 * w + mi * 16 + g, r_hi = r_lo + 8;
                #pragma unroll
                for (int nt = 0; nt < 4; nt++) {
                    int c = j0 + nt * 8 + t * 2;
                    if (c     > r_lo) s[mi][nt][0] = -1e9f;
                    if (c + 1 > r_lo) s[mi][nt][1] = -1e9f;
                    if (c     > r_hi) s[mi][nt][2] = -1e9f;
                    if (c + 1 > r_hi) s[mi][nt][3] = -1e9f;
                }
            }
        }

        // ---- online softmax per m-tile ----
        #pragma unroll
        for (int mi = 0; mi < 2; mi++) {
            float mt0 = -1e30f, mt1 = -1e30f;
            #pragma unroll
            for (int nt = 0; nt < 4; nt++) {
                mt0 = fmaxf(mt0, fmaxf(s[mi][nt][0], s[mi][nt][1]));
                mt1 = fmaxf(mt1, fmaxf(s[mi][nt][2], s[mi][nt][3]));
            }
            mt0 = fmaxf(mt0, __shfl_xor_sync(0xffffffffu, mt0, 1));
            mt0 = fmaxf(mt0, __shfl_xor_sync(0xffffffffu, mt0, 2));
            mt1 = fmaxf(mt1, __shfl_xor_sync(0xffffffffu, mt1, 1));
            mt1 = fmaxf(mt1, __shfl_xor_sync(0xffffffffu, mt1, 2));

            float mn0 = fmaxf(m[mi][0], mt0), mn1 = fmaxf(m[mi][1], mt1);
            float al0 = __expf(m[mi][0] - mn0), al1 = __expf(m[mi][1] - mn1);
            m[mi][0] = mn0; m[mi][1] = mn1;

            float rs0 = 0.f, rs1 = 0.f;
            #pragma unroll
            for (int nt = 0; nt < 4; nt++) {
                s[mi][nt][0] = __expf(s[mi][nt][0] - mn0);
                s[mi][nt][1] = __expf(s[mi][nt][1] - mn0);
                s[mi][nt][2] = __expf(s[mi][nt][2] - mn1);
                s[mi][nt][3] = __expf(s[mi][nt][3] - mn1);
                rs0 += s[mi][nt][0] + s[mi][nt][1];
                rs1 += s[mi][nt][2] + s[mi][nt][3];
            }
            rs0 += __shfl_xor_sync(0xffffffffu, rs0, 1);
            rs0 += __shfl_xor_sync(0xffffffffu, rs0, 2);
            rs1 += __shfl_xor_sync(0xffffffffu, rs1, 1);
            rs1 += __shfl_xor_sync(0xffffffffu, rs1, 2);
            l[mi][0] = l[mi][0] * al0 + rs0;
            l[mi][1] = l[mi][1] * al1 + rs1;
            #pragma unroll
            for (int nt = 0; nt < 8; nt++) {
                o[mi][nt][0] *= al0; o[mi][nt][1] *= al0;
                o[mi][nt][2] *= al1; o[mi][nt][3] *= al1;
            }

            // stage P rows of this m-tile (tf32-rounded through registers)
            #pragma unroll
            for (int nt = 0; nt < 4; nt++) {
                int c = nt * 8 + t * 2;
                *(float2*)&Ps[(32 * w + mi * 16 + g) * 36 + c] =
                    make_float2(f2tff(s[mi][nt][0]), f2tff(s[mi][nt][1]));
                *(float2*)&Ps[(32 * w + mi * 16 + 8 + g) * 36 + c] =
                    make_float2(f2tff(s[mi][nt][2]), f2tff(s[mi][nt][3]));
            }
        }
        __syncwarp();

        // ---- O += P V (32 x 64 per warp) ----
        #pragma unroll
        for (int kt = 0; kt < 4; kt++) {
            uint32_t a[2][4];
            #pragma unroll
            for (int mi = 0; mi < 2; mi++) {
                int ab = (32 * w + mi * 16 + g) * 36 + kt * 8 + t;
                a[mi][0] = __float_as_uint(Ps[ab]);
                a[mi][1] = __float_as_uint(Ps[ab + 8 * 36]);
                a[mi][2] = __float_as_uint(Ps[ab + 4]);
                a[mi][3] = __float_as_uint(Ps[ab + 8 * 36 + 4]);
            }
            #pragma unroll
            for (int nt = 0; nt < 8; nt++) {
                int bb = (nt * 8 + g) * 36 + kt * 8 + t;
                uint32_t b0 = __float_as_uint(V[bb]);
                uint32_t b1 = __float_as_uint(V[bb + 4]);
                mma_tf32(o[0][nt], a[0][0], a[0][1], a[0][2], a[0][3], b0, b1);
                mma_tf32(o[1][nt], a[1][0], a[1][1], a[1][2], a[1][3], b0, b1);
            }
        }
    }

    // ---- epilogue: normalize, transpose into Qs (O^T [d][i] ld 264), store ----
    __syncthreads();   // all warps done reading Qs
    #pragma unroll
    for (int mi = 0; mi < 2; mi++) {
        float inv0 = 1.f / l[mi][0], inv1 = 1.f / l[mi][1];
        int i_lo = 32 * w + mi * 16 + g, i_hi = i_lo + 8;
        #pragma unroll
        for (int nt = 0; nt < 8; nt++) {
            int d = nt * 8 + t * 2;
            Qs[(d)     * 264 + i_lo] = o[mi][nt][0] * inv0;
            Qs[(d + 1) * 264 + i_lo] = o[mi][nt][1] * inv0;
            Qs[(d)     * 264 + i_hi] = o[mi][nt][2] * inv1;
            Qs[(d + 1) * 264 + i_hi] = o[mi][nt][3] * inv1;
        }
    }
    __syncthreads();

    float* Og = out + ((size_t)b * E_DIM + h * HD) * N_TOK + i0;
    #pragma unroll
    for (int r = 0; r < 16; r++) {
        int idx = r * 256 + tid;
        int d = idx >> 6, i4 = idx & 63;
        float4 v = *(const float4*)&Qs[d * 264 + i4 * 4];
        *(float4*)(Og + (size_t)d * N_TOK + i4 * 4) = v;
    }
}

extern "C" void kernel_launch(void* const* d_in, const int* in_sizes, int n_in,
                              void* d_out, int out_size) {
    const float* query = (const float*)d_in[0];
    const float* key   = (const float*)d_in[1];
    const float* Wq    = (const float*)d_in[2];
    const float* bq    = (const float*)d_in[3];
    const float* Wk    = (const float*)d_in[4];
    const float* bk    = (const float*)d_in[5];
    const float* Wv    = (const float*)d_in[6];
    const float* bv    = (const float*)d_in[7];
    float* out = (float*)d_out;

    float *dTQ, *dTK, *dW;
    cudaGetSymbolAddress((void**)&dTQ, g_TQ);
    cudaGetSymbolAddress((void**)&dTK, g_TK);
    cudaGetSymbolAddress((void**)&dW,  g_W);

    const int nT4 = B_SZ * C_DIM * N_TOK / 4;     // 1M
    const int nW4 = E_DIM * C_DIM / 4;            // 64K
    round_kernel<<<2048, 256>>>(dTQ, query, nT4);
    round_kernel<<<2048, 256>>>(dTK, key,   nT4);
    round_kernel<<<512, 256>>>(dW,           Wq, nW4);
    round_kernel<<<512, 256>>>(dW + E_DIM * C_DIM,     Wk, nW4);
    round_kernel<<<512, 256>>>(dW + 2 * E_DIM * C_DIM, Wv, nW4);

    const int proj_smem = (9216 + 8704) * (int)sizeof(float);     // 71680
    cudaFuncSetAttribute(proj_kernel, cudaFuncAttributeMaxDynamicSharedMemorySize,
                         proj_smem);
    proj_kernel<<<dim3(N_TOK / 128, E_DIM / 128, 3 * B_SZ), 256, proj_smem>>>(
        bq, bk, bv);

    const int attn_smem = 35840 * (int)sizeof(float);             // 143360
    cudaFuncSetAttribute(attn_kernel, cudaFuncAttributeMaxDynamicSharedMemorySize,
                         attn_smem);
    attn_kernel<<<dim3(N_TOK / 256, NH, B_SZ), 256, attn_smem>>>(out);
}